// round 16
// baseline (speedup 1.0000x reference)
#include <cuda_runtime.h>
#include <cuda_bf16.h>
#include <cuda_fp16.h>

#define NN   50000
#define FF   500
#define EE   1600000
#define PEE  400000
#define H1D  128
#define H2D  64
#define KPAD 512
#define KSEG 4
#define SCAN_B 196

#define AST 40
#define BST 136
#define A_ELEM (64 * AST)            // 2560 bf16 per stage
#define B_ELEM (32 * BST)            // 4352 bf16 per stage
#define G1_SMEM_ELEMS (2 * (2 * A_ELEM + 2 * B_ELEM))
#define G1_SMEM_BYTES (G1_SMEM_ELEMS * 2)   // 55296 B

typedef unsigned long long ull;
typedef unsigned int uint;

// ---------------- scratch ---------------------------------------------------
__device__ __align__(16) float  g_Wg  [KPAD * H1D];
__device__ __align__(16) __half g_xW1h[NN * H1D];
__device__ __align__(16) __half g_h1h [NN * H1D];
__device__ __align__(16) __half g_hl2h[NN * H2D];
__device__ __align__(16) __half g_feath[NN * H2D];
__device__ __align__(16) float  g_hl3 [NN * 8];
__device__            float g_dinv[NN];
__device__            int   g_deg [NN];
__device__            int   g_rowptr[NN + 1];
__device__            int   g_cursor[NN];
__device__            int   g_csr[EE];
__device__            int   g_nodescan[NN];
__device__            int   g_bsum[256];
__device__            int   g_boff[256];

// ---------------- helpers ---------------------------------------------------
__device__ __forceinline__ void fma2(ull& acc, ull a, ull b) {
    asm("fma.rn.f32x2 %0, %1, %2, %3;" : "=l"(acc) : "l"(a), "l"(b), "l"(acc));
}
__device__ __forceinline__ ull dupf(float x) {
    ull r; asm("mov.b64 %0, {%1, %1};" : "=l"(r) : "f"(x)); return r;
}
__device__ __forceinline__ float2 h2f(uint u) {
    return __half22float2(*(__half2*)&u);
}
__device__ __forceinline__ uint f2h(float a, float b) {
    __half2 h = __floats2half2_rn(a, b); return *(uint*)&h;
}
__device__ __forceinline__ void red_add_f(float* a, float v) {
    asm volatile("red.global.add.f32 [%0], %1;" :: "l"(a), "f"(v) : "memory");
}
__device__ __forceinline__ void ldsm_x4(uint& r0, uint& r1, uint& r2, uint& r3, const void* p) {
    uint addr = (uint)__cvta_generic_to_shared(p);
    asm volatile("ldmatrix.sync.aligned.m8n8.x4.shared.b16 {%0,%1,%2,%3}, [%4];"
                 : "=r"(r0), "=r"(r1), "=r"(r2), "=r"(r3) : "r"(addr));
}
__device__ __forceinline__ void ldsm_x4t(uint& r0, uint& r1, uint& r2, uint& r3, const void* p) {
    uint addr = (uint)__cvta_generic_to_shared(p);
    asm volatile("ldmatrix.sync.aligned.m8n8.x4.trans.shared.b16 {%0,%1,%2,%3}, [%4];"
                 : "=r"(r0), "=r"(r1), "=r"(r2), "=r"(r3) : "r"(addr));
}
__device__ __forceinline__ void mma16816(float* c, const uint* a, const uint* b) {
    asm volatile("mma.sync.aligned.m16n8k16.row.col.f32.bf16.bf16.f32 "
                 "{%0,%1,%2,%3}, {%4,%5,%6,%7}, {%8,%9}, {%0,%1,%2,%3};"
                 : "+f"(c[0]), "+f"(c[1]), "+f"(c[2]), "+f"(c[3])
                 : "r"(a[0]), "r"(a[1]), "r"(a[2]), "r"(a[3]), "r"(b[0]), "r"(b[1]));
}
__device__ __forceinline__ void bf16split(float v, __nv_bfloat16& h, __nv_bfloat16& l) {
    h = __float2bfloat16(v);
    l = __float2bfloat16(v - __bfloat162float(h));
}
__device__ __forceinline__ void split_store4(const float4& v, __nv_bfloat16* ph, __nv_bfloat16* pl) {
    __nv_bfloat162 h01, h23, l01, l23;
    __nv_bfloat16 h, l;
    bf16split(v.x, h, l); h01.x = h; l01.x = l;
    bf16split(v.y, h, l); h01.y = h; l01.y = l;
    bf16split(v.z, h, l); h23.x = h; l23.x = l;
    bf16split(v.w, h, l); h23.y = h; l23.y = l;
    *(uint2*)ph = make_uint2(*(uint*)&h01, *(uint*)&h23);
    *(uint2*)pl = make_uint2(*(uint*)&l01, *(uint*)&l23);
}

// ---------------- merged init: zero Wg + deg --------------------------------
__global__ void k_init() {
    int i = blockIdx.x * blockDim.x + threadIdx.x;
    if (i < KPAD * H1D) g_Wg[i] = 0.f;
    if (i < NN) g_deg[i] = 0;
}

// ---------------- CSR build -------------------------------------------------
__global__ void k_deg(const int* __restrict__ dst) {
    int e = blockIdx.x * blockDim.x + threadIdx.x;
    if (e < EE) atomicAdd(&g_deg[dst[e]], 1);
}
__global__ void __launch_bounds__(256) k_scan1() {
    __shared__ int sh[256];
    int i = blockIdx.x * 256 + threadIdx.x;
    int t = threadIdx.x;
    int d = (i < NN) ? g_deg[i] : 0;
    sh[t] = d;
    if (i < NN) g_dinv[i] = rsqrtf((float)(d + 1));
    __syncthreads();
    #pragma unroll
    for (int off = 1; off < 256; off <<= 1) {
        int u = (t >= off) ? sh[t - off] : 0;
        __syncthreads();
        sh[t] += u;
        __syncthreads();
    }
    if (i < NN) g_nodescan[i] = sh[t];
    if (t == 255) g_bsum[blockIdx.x] = sh[255];
}
__global__ void __launch_bounds__(256) k_scan2() {
    __shared__ int sh[256];
    int t = threadIdx.x;
    sh[t] = (t < SCAN_B) ? g_bsum[t] : 0;
    __syncthreads();
    #pragma unroll
    for (int off = 1; off < 256; off <<= 1) {
        int u = (t >= off) ? sh[t - off] : 0;
        __syncthreads();
        sh[t] += u;
        __syncthreads();
    }
    g_boff[t] = (t > 0) ? sh[t - 1] : 0;
}
__global__ void __launch_bounds__(256) k_scan3() {
    int i = blockIdx.x * 256 + threadIdx.x;
    if (i < NN) {
        int rp = g_boff[blockIdx.x] + g_nodescan[i] - g_deg[i];
        g_rowptr[i] = rp;
        g_cursor[i] = rp;
    }
    if (i == 0) g_rowptr[NN] = EE;
}
__global__ void k_scatter(const int* __restrict__ src, const int* __restrict__ dst) {
    int e = blockIdx.x * blockDim.x + threadIdx.x;
    if (e >= EE) return;
    int d = dst[e];
    int p = atomicAdd(&g_cursor[d], 1);
    g_csr[p] = src[e];
}

// ---------------- Wg: split-K red.add ---------------------------------------
__global__ void k_wg(const float* __restrict__ glove, const float* __restrict__ W1) {
    int idx = blockIdx.x * blockDim.x + threadIdx.x;
    if (idx >= FF * H1D) return;
    int f = idx / H1D, h = idx % H1D;
    int kb = blockIdx.y * 125;
    float a0 = 0.f, a1 = 0.f;
    const float* gr = glove + f * FF;
    #pragma unroll 5
    for (int k = 0; k < 124; k += 2) {
        a0 += gr[kb + k]     * W1[(kb + k) * H1D + h];
        a1 += gr[kb + k + 1] * W1[(kb + k + 1) * H1D + h];
    }
    a0 += gr[kb + 124] * W1[(kb + 124) * H1D + h];
    red_add_f(&g_Wg[idx], a0 + a1);
}

// ---------------- GEMM1 (tensor, bf16x3, BM=64, 2mx4n, DOUBLE-BUFFERED) -----
__global__ void __launch_bounds__(256, 2) k_gemm1(const float* __restrict__ A) {
    extern __shared__ __align__(16) __nv_bfloat16 smem[];
    __nv_bfloat16* bAh = smem;                              // [2][A_ELEM]
    __nv_bfloat16* bAl = smem + 2 * A_ELEM;
    __nv_bfloat16* bBh = smem + 4 * A_ELEM;                 // [2][B_ELEM]
    __nv_bfloat16* bBl = smem + 4 * A_ELEM + 2 * B_ELEM;

    const int tid  = threadIdx.x;
    const int lane = tid & 31;
    const int wid  = tid >> 5;
    const int row0 = blockIdx.x * 64;
    const int wm = (wid & 1) * 32;
    const int wn = (wid >> 1) * 32;

    float c[2][4][4];
    #pragma unroll
    for (int mi = 0; mi < 2; mi++)
        #pragma unroll
        for (int ni = 0; ni < 4; ni++)
            #pragma unroll
            for (int q = 0; q < 4; q++) c[mi][ni][q] = 0.f;

    // per-thread tile coords
    const int ar0 = tid >> 3,  ac0 = (tid & 7) << 2;        // A: 2 float4/thread
    const int ar1 = (tid + 256) >> 3, ac1 = ((tid + 256) & 7) << 2;
    float4 ra[2], rb[4];

    // ---- prologue: tile 0 -> regs -> stage 0 ----
    {
        int gr = row0 + ar0;
        ra[0] = make_float4(0.f, 0.f, 0.f, 0.f);
        if (gr < NN && ac0 + 4 <= FF) ra[0] = *(const float4*)(A + gr * FF + ac0);
        gr = row0 + ar1;
        ra[1] = make_float4(0.f, 0.f, 0.f, 0.f);
        if (gr < NN && ac1 + 4 <= FF) ra[1] = *(const float4*)(A + gr * FF + ac1);
        #pragma unroll
        for (int i = 0; i < 4; i++) {
            int lin = tid + i * 256;
            int br = lin >> 5, bc = (lin & 31) << 2;
            rb[i] = *(const float4*)(g_Wg + br * H1D + bc);
        }
        split_store4(ra[0], bAh + ar0 * AST + ac0, bAl + ar0 * AST + ac0);
        split_store4(ra[1], bAh + ar1 * AST + ac1, bAl + ar1 * AST + ac1);
        #pragma unroll
        for (int i = 0; i < 4; i++) {
            int lin = tid + i * 256;
            int br = lin >> 5, bc = (lin & 31) << 2;
            split_store4(rb[i], bBh + br * BST + bc, bBl + br * BST + bc);
        }
    }
    __syncthreads();

    // prefetch tile 1 into regs
    {
        int gr = row0 + ar0, gc = 32 + ac0;
        ra[0] = make_float4(0.f, 0.f, 0.f, 0.f);
        if (gr < NN && gc + 4 <= FF) ra[0] = *(const float4*)(A + gr * FF + gc);
        gr = row0 + ar1; gc = 32 + ac1;
        ra[1] = make_float4(0.f, 0.f, 0.f, 0.f);
        if (gr < NN && gc + 4 <= FF) ra[1] = *(const float4*)(A + gr * FF + gc);
        #pragma unroll
        for (int i = 0; i < 4; i++) {
            int lin = tid + i * 256;
            int br = lin >> 5, bc = (lin & 31) << 2;
            rb[i] = *(const float4*)(g_Wg + (32 + br) * H1D + bc);
        }
    }

    int p = 0;
    for (int k0 = 0; k0 < KPAD; k0 += 32) {
        const __nv_bfloat16* sAh = bAh + p * A_ELEM;
        const __nv_bfloat16* sAl = bAl + p * A_ELEM;
        const __nv_bfloat16* sBh = bBh + p * B_ELEM;
        const __nv_bfloat16* sBl = bBl + p * B_ELEM;

        // compute on stage p
        #pragma unroll
        for (int kk = 0; kk < 32; kk += 16) {
            uint ah[2][4], al[2][4], bh[4][2], bl[4][2];
            #pragma unroll
            for (int mi = 0; mi < 2; mi++) {
                const __nv_bfloat16* pa = sAh + (wm + mi * 16 + (lane & 15)) * AST + kk + ((lane >> 4) << 3);
                ldsm_x4(ah[mi][0], ah[mi][1], ah[mi][2], ah[mi][3], pa);
                const __nv_bfloat16* pb = sAl + (wm + mi * 16 + (lane & 15)) * AST + kk + ((lane >> 4) << 3);
                ldsm_x4(al[mi][0], al[mi][1], al[mi][2], al[mi][3], pb);
            }
            #pragma unroll
            for (int ni = 0; ni < 4; ni += 2) {
                const __nv_bfloat16* pbh = sBh + (kk + (lane & 15)) * BST + wn + ni * 8 + ((lane >> 4) << 3);
                ldsm_x4t(bh[ni][0], bh[ni][1], bh[ni + 1][0], bh[ni + 1][1], pbh);
                const __nv_bfloat16* pbl = sBl + (kk + (lane & 15)) * BST + wn + ni * 8 + ((lane >> 4) << 3);
                ldsm_x4t(bl[ni][0], bl[ni][1], bl[ni + 1][0], bl[ni + 1][1], pbl);
            }
            #pragma unroll
            for (int mi = 0; mi < 2; mi++)
                #pragma unroll
                for (int ni = 0; ni < 4; ni++) {
                    mma16816(c[mi][ni], ah[mi], bh[ni]);
                    mma16816(c[mi][ni], ah[mi], bl[ni]);
                    mma16816(c[mi][ni], al[mi], bh[ni]);
                }
        }

        // store tile kn (in regs) into stage p^1; prefetch tile kn+32
        int kn = k0 + 32;
        if (kn < KPAD) {
            __nv_bfloat16* dAh = bAh + (p ^ 1) * A_ELEM;
            __nv_bfloat16* dAl = bAl + (p ^ 1) * A_ELEM;
            __nv_bfloat16* dBh = bBh + (p ^ 1) * B_ELEM;
            __nv_bfloat16* dBl = bBl + (p ^ 1) * B_ELEM;
            split_store4(ra[0], dAh + ar0 * AST + ac0, dAl + ar0 * AST + ac0);
            split_store4(ra[1], dAh + ar1 * AST + ac1, dAl + ar1 * AST + ac1);
            #pragma unroll
            for (int i = 0; i < 4; i++) {
                int lin = tid + i * 256;
                int br = lin >> 5, bc = (lin & 31) << 2;
                split_store4(rb[i], dBh + br * BST + bc, dBl + br * BST + bc);
            }
            int km = kn + 32;
            if (km < KPAD) {
                int gr = row0 + ar0, gc = km + ac0;
                ra[0] = make_float4(0.f, 0.f, 0.f, 0.f);
                if (gr < NN && gc + 4 <= FF) ra[0] = *(const float4*)(A + gr * FF + gc);
                gr = row0 + ar1; gc = km + ac1;
                ra[1] = make_float4(0.f, 0.f, 0.f, 0.f);
                if (gr < NN && gc + 4 <= FF) ra[1] = *(const float4*)(A + gr * FF + gc);
                #pragma unroll
                for (int i = 0; i < 4; i++) {
                    int lin = tid + i * 256;
                    int br = lin >> 5, bc = (lin & 31) << 2;
                    rb[i] = *(const float4*)(g_Wg + (km + br) * H1D + bc);
                }
            }
            __syncthreads();
        }
        p ^= 1;
    }

    #pragma unroll
    for (int mi = 0; mi < 2; mi++) {
        int r_lo = row0 + wm + mi * 16 + (lane >> 2);
        #pragma unroll
        for (int ni = 0; ni < 4; ni++) {
            int col = wn + ni * 8 + ((lane & 3) << 1);
            if (r_lo < NN)
                *(uint*)(g_xW1h + r_lo * H1D + col) = f2h(c[mi][ni][0], c[mi][ni][1]);
            if (r_lo + 8 < NN)
                *(uint*)(g_xW1h + (r_lo + 8) * H1D + col) = f2h(c[mi][ni][2], c[mi][ni][3]);
        }
    }
}

// ---------------- agg1: h1h = relu(Agg(xW1h) + b1), fp16 io -----------------
__global__ void k_agg1(const float* __restrict__ b1) {
    int n    = (blockIdx.x * blockDim.x + threadIdx.x) >> 5;
    int lane = threadIdx.x & 31;
    if (n >= NN) return;
    int r0 = g_rowptr[n], r1 = g_rowptr[n + 1];
    float4 s4 = make_float4(0.f, 0.f, 0.f, 0.f);
    int j = r0;
    for (; j + 1 < r1; j += 2) {
        int sa = g_csr[j], sb = g_csr[j + 1];
        float wa = g_dinv[sa], wb = g_dinv[sb];
        uint2 ua = *(const uint2*)(g_xW1h + sa * H1D + lane * 4);
        uint2 ub = *(const uint2*)(g_xW1h + sb * H1D + lane * 4);
        float2 a01 = h2f(ua.x), a23 = h2f(ua.y);
        float2 b01 = h2f(ub.x), b23 = h2f(ub.y);
        s4.x += wa * a01.x + wb * b01.x;
        s4.y += wa * a01.y + wb * b01.y;
        s4.z += wa * a23.x + wb * b23.x;
        s4.w += wa * a23.y + wb * b23.y;
    }
    if (j < r1) {
        int sa = g_csr[j];
        float wa = g_dinv[sa];
        uint2 ua = *(const uint2*)(g_xW1h + sa * H1D + lane * 4);
        float2 a01 = h2f(ua.x), a23 = h2f(ua.y);
        s4.x += wa * a01.x; s4.y += wa * a01.y; s4.z += wa * a23.x; s4.w += wa * a23.y;
    }
    float dn = g_dinv[n], dn2 = dn * dn;
    uint2 us = *(const uint2*)(g_xW1h + n * H1D + lane * 4);
    float2 s01 = h2f(us.x), s23 = h2f(us.y);
    float4 bv = *(const float4*)(b1 + lane * 4);
    float o0 = fmaxf(dn * s4.x + dn2 * s01.x + bv.x, 0.f);
    float o1 = fmaxf(dn * s4.y + dn2 * s01.y + bv.y, 0.f);
    float o2 = fmaxf(dn * s4.z + dn2 * s23.x + bv.z, 0.f);
    float o3 = fmaxf(dn * s4.w + dn2 * s23.y + bv.w, 0.f);
    *(uint2*)(g_h1h + n * H1D + lane * 4) = make_uint2(f2h(o0, o1), f2h(o2, o3));
}

// ---------------- GEMM2 (f32x2, fp16 in/out) --------------------------------
__global__ void __launch_bounds__(256) k_gemm2(const float* __restrict__ W2) {
    __shared__ float As[8][128 + 4];
    __shared__ float Bs[8][64];
    const int tid  = threadIdx.x;
    const int row0 = blockIdx.x * 128;
    const int tx = tid & 15, ty = tid >> 4;

    ull accp[8][2];
    #pragma unroll
    for (int i = 0; i < 8; i++) { accp[i][0] = 0ull; accp[i][1] = 0ull; }

    const int arow = tid >> 1, acol = (tid & 1) << 2;
    const int brow = tid >> 5, bcol = (tid & 31) << 1;

    for (int k0 = 0; k0 < H1D; k0 += 8) {
        float2 v01 = make_float2(0.f, 0.f), v23 = make_float2(0.f, 0.f);
        int gr = row0 + arow;
        if (gr < NN) {
            uint2 ua = *(const uint2*)(g_h1h + gr * H1D + k0 + acol);
            v01 = h2f(ua.x); v23 = h2f(ua.y);
        }
        As[acol + 0][arow] = v01.x;
        As[acol + 1][arow] = v01.y;
        As[acol + 2][arow] = v23.x;
        As[acol + 3][arow] = v23.y;
        *(float2*)&Bs[brow][bcol] = *(const float2*)(W2 + (k0 + brow) * H2D + bcol);
        __syncthreads();
        #pragma unroll
        for (int kk = 0; kk < 8; kk++) {
            float ra[8];
            ull rb2[2];
            *(float4*)&ra[0] = *(const float4*)&As[kk][ty * 8 + 0];
            *(float4*)&ra[4] = *(const float4*)&As[kk][ty * 8 + 4];
            rb2[0] = *(const ull*)&Bs[kk][tx * 4 + 0];
            rb2[1] = *(const ull*)&Bs[kk][tx * 4 + 2];
            #pragma unroll
            for (int i = 0; i < 8; i++) {
                ull a2 = dupf(ra[i]);
                fma2(accp[i][0], a2, rb2[0]);
                fma2(accp[i][1], a2, rb2[1]);
            }
        }
        __syncthreads();
    }
    #pragma unroll
    for (int i = 0; i < 8; i++) {
        int r = row0 + ty * 8 + i;
        if (r < NN) {
            float x0, x1, x2, x3;
            asm("mov.b64 {%0,%1}, %2;" : "=f"(x0), "=f"(x1) : "l"(accp[i][0]));
            asm("mov.b64 {%0,%1}, %2;" : "=f"(x2), "=f"(x3) : "l"(accp[i][1]));
            *(uint2*)(g_hl2h + r * H2D + tx * 4) = make_uint2(f2h(x0, x1), f2h(x2, x3));
        }
    }
}

// ---------------- agg2 + fused small3: feat (fp32 out) + feath + hl3 --------
__global__ void k_agg2(const float* __restrict__ b2, float* __restrict__ feat,
                       const float* __restrict__ Wr, const float* __restrict__ Wk) {
    __shared__ float sW[64 * 6];
    for (int t = threadIdx.x; t < 384; t += blockDim.x) {
        int k = t / 6, c = t % 6;
        sW[t] = (c < 3) ? Wr[k * 3 + c] : Wk[k * 3 + (c - 3)];
    }
    __syncthreads();

    int n    = (blockIdx.x * blockDim.x + threadIdx.x) >> 5;
    int lane = threadIdx.x & 31;
    if (n >= NN) return;
    int r0 = g_rowptr[n], r1 = g_rowptr[n + 1];
    float2 s2 = make_float2(0.f, 0.f);
    int j = r0;
    for (; j + 1 < r1; j += 2) {
        int sa = g_csr[j], sb = g_csr[j + 1];
        float wa = g_dinv[sa], wb = g_dinv[sb];
        float2 va = h2f(*(const uint*)(g_hl2h + sa * H2D + lane * 2));
        float2 vb = h2f(*(const uint*)(g_hl2h + sb * H2D + lane * 2));
        s2.x += wa * va.x + wb * vb.x;
        s2.y += wa * va.y + wb * vb.y;
    }
    if (j < r1) {
        int sa = g_csr[j];
        float wa = g_dinv[sa];
        float2 va = h2f(*(const uint*)(g_hl2h + sa * H2D + lane * 2));
        s2.x += wa * va.x; s2.y += wa * va.y;
    }
    float dn = g_dinv[n], dn2 = dn * dn;
    float2 self = h2f(*(const uint*)(g_hl2h + n * H2D + lane * 2));
    float2 bv   = *(const float2*)(b2 + lane * 2);
    float2 o;
    o.x = dn * s2.x + dn2 * self.x + bv.x;
    o.y = dn * s2.y + dn2 * self.y + bv.y;
    *(float2*)(feat + n * H2D + lane * 2) = o;
    *(uint*)(g_feath + n * H2D + lane * 2) = f2h(o.x, o.y);

    float p[6];
    #pragma unroll
    for (int c = 0; c < 6; c++)
        p[c] = o.x * sW[(2 * lane) * 6 + c] + o.y * sW[(2 * lane + 1) * 6 + c];
    #pragma unroll
    for (int off = 16; off > 0; off >>= 1) {
        #pragma unroll
        for (int c = 0; c < 6; c++)
            p[c] += __shfl_xor_sync(0xffffffffu, p[c], off);
    }
    if (lane == 0) {
        *(float4*)(g_hl3 + n * 8)     = make_float4(p[0], p[1], p[2], p[3]);
        *(float4*)(g_hl3 + n * 8 + 4) = make_float4(p[4], p[5], 0.f, 0.f);
    }
}

// ---------------- agg3 + log_softmax + outputs ------------------------------
__global__ void k_agg3(const float* __restrict__ ba, const float* __restrict__ bk,
                       float* __restrict__ attr_o, float* __restrict__ att_o) {
    int n = blockIdx.x * blockDim.x + threadIdx.x;
    if (n >= NN) return;
    int r0 = g_rowptr[n], r1 = g_rowptr[n + 1];
    float4 s0 = make_float4(0.f, 0.f, 0.f, 0.f);
    float2 s1 = make_float2(0.f, 0.f);
    for (int j = r0; j < r1; j++) {
        int s = g_csr[j];
        float w = g_dinv[s];
        float4 v0 = *(const float4*)(g_hl3 + s * 8);
        float2 v1 = *(const float2*)(g_hl3 + s * 8 + 4);
        s0.x += w * v0.x; s0.y += w * v0.y; s0.z += w * v0.z; s0.w += w * v0.w;
        s1.x += w * v1.x; s1.y += w * v1.y;
    }
    float dn = g_dinv[n], dn2 = dn * dn;
    float4 e0 = *(const float4*)(g_hl3 + n * 8);
    float2 e1 = *(const float2*)(g_hl3 + n * 8 + 4);
    float v0 = dn * s0.x + dn2 * e0.x + ba[0];
    float v1 = dn * s0.y + dn2 * e0.y + ba[1];
    float v2 = dn * s0.z + dn2 * e0.z + ba[2];
    float v3 = dn * s0.w + dn2 * e0.w + bk[0];
    float v4 = dn * s1.x + dn2 * e1.x + bk[1];
    float v5 = dn * s1.y + dn2 * e1.y + bk[2];
    float m  = fmaxf(v0, fmaxf(v1, v2));
    float ls = m + logf(expf(v0 - m) + expf(v1 - m) + expf(v2 - m));
    attr_o[n * 3 + 0] = v0 - ls;
    attr_o[n * 3 + 1] = v1 - ls;
    attr_o[n * 3 + 2] = v2 - ls;
    att_o[n * 3 + 0] = v3;
    att_o[n * 3 + 1] = v4;
    att_o[n * 3 + 2] = v5;
}

// ---------------- edge dot products (fp16 gather, 8 lanes x 16B) ------------
__global__ void k_dot(const int* __restrict__ pe, const int* __restrict__ ne,
                      float* __restrict__ res) {
    int t = blockIdx.x * blockDim.x + threadIdx.x;
    int e = t >> 3, l = t & 7;
    if (e >= 2 * PEE) return;
    int i, j;
    if (e < PEE) { j = pe[e];        i = pe[PEE + e]; }
    else         { j = ne[e - PEE];  i = ne[PEE + (e - PEE)]; }
    uint4 ua = *(const uint4*)(g_feath + i * H2D + l * 8);
    uint4 ub = *(const uint4*)(g_feath + j * H2D + l * 8);
    float2 a0 = h2f(ua.x), a1 = h2f(ua.y), a2 = h2f(ua.z), a3 = h2f(ua.w);
    float2 b0 = h2f(ub.x), b1 = h2f(ub.y), b2 = h2f(ub.z), b3 = h2f(ub.w);
    float p = a0.x * b0.x + a0.y * b0.y + a1.x * b1.x + a1.y * b1.y
            + a2.x * b2.x + a2.y * b2.y + a3.x * b3.x + a3.y * b3.y;
    p += __shfl_xor_sync(0xffffffffu, p, 4);
    p += __shfl_xor_sync(0xffffffffu, p, 2);
    p += __shfl_xor_sync(0xffffffffu, p, 1);
    if (l == 0) res[e] = p;
}

// ---------------- streams / events (after kernels: set smem attribute) ------
static cudaStream_t g_s2;
static cudaEvent_t  g_evFork, g_evJoin, g_evFork2, g_evJoin2;
namespace {
struct StreamInit {
    StreamInit() {
        cudaStreamCreateWithFlags(&g_s2, cudaStreamNonBlocking);
        cudaEventCreateWithFlags(&g_evFork,  cudaEventDisableTiming);
        cudaEventCreateWithFlags(&g_evJoin,  cudaEventDisableTiming);
        cudaEventCreateWithFlags(&g_evFork2, cudaEventDisableTiming);
        cudaEventCreateWithFlags(&g_evJoin2, cudaEventDisableTiming);
        cudaFuncSetAttribute(k_gemm1, cudaFuncAttributeMaxDynamicSharedMemorySize,
                             G1_SMEM_BYTES);
    }
} s_streamInit;
}

// ---------------- launch -----------------------------------------------------
extern "C" void kernel_launch(void* const* d_in, const int* in_sizes, int n_in,
                              void* d_out, int out_size) {
    const float* x      = (const float*)d_in[0];
    const float* glove  = (const float*)d_in[1];
    const float* W1     = (const float*)d_in[2];
    const float* b1     = (const float*)d_in[3];
    const float* W2     = (const float*)d_in[4];
    const float* b2     = (const float*)d_in[5];
    const float* W_attr = (const float*)d_in[6];
    const float* b_attr = (const float*)d_in[7];
    const float* W_attk = (const float*)d_in[8];
    const float* b_attk = (const float*)d_in[9];
    const int*   ei     = (const int*)d_in[10];
    const int*   pe     = (const int*)d_in[11];
    const int*   ne     = (const int*)d_in[12];

    float* out    = (float*)d_out;
    float* res    = out;
    float* attr_o = out + 2 * PEE;
    float* att_o  = attr_o + NN * 3;
    float* feat   = att_o + NN * 3;

    const int* src = ei;
    const int* dst = ei + EE;

    k_init<<<(KPAD * H1D + 255) / 256, 256>>>();                       // 1 (main)
    cudaEventRecord(g_evFork, 0);
    cudaStreamWaitEvent(g_s2, g_evFork, 0);

    {
        dim3 g((FF * H1D + 255) / 256, KSEG);
        k_wg <<<g, 256>>>(glove, W1);                                  // 2 (main)
    }
    k_deg    <<<(EE + 255) / 256, 256, 0, g_s2>>>(dst);                // 3 (side)
    k_gemm1  <<<(NN + 63) / 64, 256, G1_SMEM_BYTES>>>(x);              // 4 (main)

    k_scan1  <<<SCAN_B, 256, 0, g_s2>>>();
    k_scan2  <<<1, 256, 0, g_s2>>>();
    k_scan3  <<<SCAN_B, 256, 0, g_s2>>>();
    k_scatter<<<(EE + 255) / 256, 256, 0, g_s2>>>(src, dst);
    cudaEventRecord(g_evJoin, g_s2);

    cudaStreamWaitEvent(0, g_evJoin, 0);

    k_agg1 <<<(NN * 32 + 255) / 256, 256>>>(b1);
    k_gemm2<<<(NN + 127) / 128, 256>>>(W2);
    k_agg2 <<<(NN * 32 + 255) / 256, 256>>>(b2, feat, W_attr, W_attk);

    cudaEventRecord(g_evFork2, 0);
    cudaStreamWaitEvent(g_s2, g_evFork2, 0);
    k_dot<<<(2 * PEE * 8 + 255) / 256, 256, 0, g_s2>>>(pe, ne, res);
    cudaEventRecord(g_evJoin2, g_s2);

    k_agg3<<<(NN + 255) / 256, 256>>>(b_attr, b_attk, attr_o, att_o);

    cudaStreamWaitEvent(0, g_evJoin2, 0);
}

// round 17
// speedup vs baseline: 1.0446x; 1.0446x over previous
#include <cuda_runtime.h>
#include <cuda_bf16.h>
#include <cuda_fp16.h>

#define NN   50000
#define FF   500
#define EE   1600000
#define PEE  400000
#define H1D  128
#define H2D  64
#define KPAD 512
#define KSEG 4
#define SCAN_B 196

#define AST 40
#define BST 136
#define A_ELEM (64 * AST)
#define B_ELEM (32 * BST)
#define G1_SMEM_ELEMS (2 * (2 * A_ELEM + 2 * B_ELEM))
#define G1_SMEM_BYTES (G1_SMEM_ELEMS * 2)   // 55296 B

#define AST2 40   // gemm2 A smem stride (fp16)
#define BST2 72   // gemm2 B smem stride (fp16)

typedef unsigned long long ull;
typedef unsigned int uint;

// ---------------- scratch ---------------------------------------------------
__device__ __align__(16) float  g_Wg  [KPAD * H1D];
__device__ __align__(16) __half g_xW1h[NN * H1D];
__device__ __align__(16) __half g_h1h [NN * H1D];
__device__ __align__(16) __half g_hl2h[NN * H2D];
__device__ __align__(16) __half g_feath[NN * H2D];
__device__ __align__(16) float  g_hl3 [NN * 8];
__device__            float g_dinv[NN];
__device__            int   g_deg [NN];
__device__            int   g_rowptr[NN + 1];
__device__            int   g_cursor[NN];
__device__            int   g_csr[EE];
__device__            int   g_nodescan[NN];
__device__            int   g_bsum[256];
__device__            int   g_boff[256];

// ---------------- helpers ---------------------------------------------------
__device__ __forceinline__ float2 h2f(uint u) {
    return __half22float2(*(__half2*)&u);
}
__device__ __forceinline__ uint f2h(float a, float b) {
    __half2 h = __floats2half2_rn(a, b); return *(uint*)&h;
}
__device__ __forceinline__ void red_add_f(float* a, float v) {
    asm volatile("red.global.add.f32 [%0], %1;" :: "l"(a), "f"(v) : "memory");
}
__device__ __forceinline__ void ldsm_x4(uint& r0, uint& r1, uint& r2, uint& r3, const void* p) {
    uint addr = (uint)__cvta_generic_to_shared(p);
    asm volatile("ldmatrix.sync.aligned.m8n8.x4.shared.b16 {%0,%1,%2,%3}, [%4];"
                 : "=r"(r0), "=r"(r1), "=r"(r2), "=r"(r3) : "r"(addr));
}
__device__ __forceinline__ void ldsm_x4t(uint& r0, uint& r1, uint& r2, uint& r3, const void* p) {
    uint addr = (uint)__cvta_generic_to_shared(p);
    asm volatile("ldmatrix.sync.aligned.m8n8.x4.trans.shared.b16 {%0,%1,%2,%3}, [%4];"
                 : "=r"(r0), "=r"(r1), "=r"(r2), "=r"(r3) : "r"(addr));
}
__device__ __forceinline__ void mma16816(float* c, const uint* a, const uint* b) {
    asm volatile("mma.sync.aligned.m16n8k16.row.col.f32.bf16.bf16.f32 "
                 "{%0,%1,%2,%3}, {%4,%5,%6,%7}, {%8,%9}, {%0,%1,%2,%3};"
                 : "+f"(c[0]), "+f"(c[1]), "+f"(c[2]), "+f"(c[3])
                 : "r"(a[0]), "r"(a[1]), "r"(a[2]), "r"(a[3]), "r"(b[0]), "r"(b[1]));
}
__device__ __forceinline__ void mma16816h(float* c, const uint* a, const uint* b) {
    asm volatile("mma.sync.aligned.m16n8k16.row.col.f32.f16.f16.f32 "
                 "{%0,%1,%2,%3}, {%4,%5,%6,%7}, {%8,%9}, {%0,%1,%2,%3};"
                 : "+f"(c[0]), "+f"(c[1]), "+f"(c[2]), "+f"(c[3])
                 : "r"(a[0]), "r"(a[1]), "r"(a[2]), "r"(a[3]), "r"(b[0]), "r"(b[1]));
}
__device__ __forceinline__ void bf16split(float v, __nv_bfloat16& h, __nv_bfloat16& l) {
    h = __float2bfloat16(v);
    l = __float2bfloat16(v - __bfloat162float(h));
}
__device__ __forceinline__ void split_store4(const float4& v, __nv_bfloat16* ph, __nv_bfloat16* pl) {
    __nv_bfloat162 h01, h23, l01, l23;
    __nv_bfloat16 h, l;
    bf16split(v.x, h, l); h01.x = h; l01.x = l;
    bf16split(v.y, h, l); h01.y = h; l01.y = l;
    bf16split(v.z, h, l); h23.x = h; l23.x = l;
    bf16split(v.w, h, l); h23.y = h; l23.y = l;
    *(uint2*)ph = make_uint2(*(uint*)&h01, *(uint*)&h23);
    *(uint2*)pl = make_uint2(*(uint*)&l01, *(uint*)&l23);
}
__device__ __forceinline__ void fp16split4(const float4& v, __half* ph, __half* pl) {
    __half2 h01, h23, l01, l23;
    __half h;
    h = __float2half_rn(v.x); h01.x = h; l01.x = __float2half_rn(v.x - __half2float(h));
    h = __float2half_rn(v.y); h01.y = h; l01.y = __float2half_rn(v.y - __half2float(h));
    h = __float2half_rn(v.z); h23.x = h; l23.x = __float2half_rn(v.z - __half2float(h));
    h = __float2half_rn(v.w); h23.y = h; l23.y = __float2half_rn(v.w - __half2float(h));
    *(uint2*)ph = make_uint2(*(uint*)&h01, *(uint*)&h23);
    *(uint2*)pl = make_uint2(*(uint*)&l01, *(uint*)&l23);
}

// ---------------- merged init: zero Wg + deg --------------------------------
__global__ void k_init() {
    int i = blockIdx.x * blockDim.x + threadIdx.x;
    if (i < KPAD * H1D) g_Wg[i] = 0.f;
    if (i < NN) g_deg[i] = 0;
}

// ---------------- CSR build -------------------------------------------------
__global__ void k_deg(const int* __restrict__ dst) {
    int e = blockIdx.x * blockDim.x + threadIdx.x;
    if (e < EE) atomicAdd(&g_deg[dst[e]], 1);
}
__global__ void __launch_bounds__(256) k_scan1() {
    __shared__ int sh[256];
    int i = blockIdx.x * 256 + threadIdx.x;
    int t = threadIdx.x;
    int d = (i < NN) ? g_deg[i] : 0;
    sh[t] = d;
    if (i < NN) g_dinv[i] = rsqrtf((float)(d + 1));
    __syncthreads();
    #pragma unroll
    for (int off = 1; off < 256; off <<= 1) {
        int u = (t >= off) ? sh[t - off] : 0;
        __syncthreads();
        sh[t] += u;
        __syncthreads();
    }
    if (i < NN) g_nodescan[i] = sh[t];
    if (t == 255) g_bsum[blockIdx.x] = sh[255];
}
__global__ void __launch_bounds__(256) k_scan2() {
    __shared__ int sh[256];
    int t = threadIdx.x;
    sh[t] = (t < SCAN_B) ? g_bsum[t] : 0;
    __syncthreads();
    #pragma unroll
    for (int off = 1; off < 256; off <<= 1) {
        int u = (t >= off) ? sh[t - off] : 0;
        __syncthreads();
        sh[t] += u;
        __syncthreads();
    }
    g_boff[t] = (t > 0) ? sh[t - 1] : 0;
}
__global__ void __launch_bounds__(256) k_scan3() {
    int i = blockIdx.x * 256 + threadIdx.x;
    if (i < NN) {
        int rp = g_boff[blockIdx.x] + g_nodescan[i] - g_deg[i];
        g_rowptr[i] = rp;
        g_cursor[i] = rp;
    }
    if (i == 0) g_rowptr[NN] = EE;
}
__global__ void k_scatter(const int* __restrict__ src, const int* __restrict__ dst) {
    int e = blockIdx.x * blockDim.x + threadIdx.x;
    if (e >= EE) return;
    int d = dst[e];
    int p = atomicAdd(&g_cursor[d], 1);
    g_csr[p] = src[e];
}

// ---------------- Wg: split-K red.add ---------------------------------------
__global__ void k_wg(const float* __restrict__ glove, const float* __restrict__ W1) {
    int idx = blockIdx.x * blockDim.x + threadIdx.x;
    if (idx >= FF * H1D) return;
    int f = idx / H1D, h = idx % H1D;
    int kb = blockIdx.y * 125;
    float a0 = 0.f, a1 = 0.f;
    const float* gr = glove + f * FF;
    #pragma unroll 5
    for (int k = 0; k < 124; k += 2) {
        a0 += gr[kb + k]     * W1[(kb + k) * H1D + h];
        a1 += gr[kb + k + 1] * W1[(kb + k + 1) * H1D + h];
    }
    a0 += gr[kb + 124] * W1[(kb + 124) * H1D + h];
    red_add_f(&g_Wg[idx], a0 + a1);
}

// ---------------- GEMM1 (tensor, bf16x3, BM=64, 2mx4n, double-buffered) -----
__global__ void __launch_bounds__(256, 2) k_gemm1(const float* __restrict__ A) {
    extern __shared__ __align__(16) __nv_bfloat16 smem[];
    __nv_bfloat16* bAh = smem;
    __nv_bfloat16* bAl = smem + 2 * A_ELEM;
    __nv_bfloat16* bBh = smem + 4 * A_ELEM;
    __nv_bfloat16* bBl = smem + 4 * A_ELEM + 2 * B_ELEM;

    const int tid  = threadIdx.x;
    const int lane = tid & 31;
    const int wid  = tid >> 5;
    const int row0 = blockIdx.x * 64;
    const int wm = (wid & 1) * 32;
    const int wn = (wid >> 1) * 32;

    float c[2][4][4];
    #pragma unroll
    for (int mi = 0; mi < 2; mi++)
        #pragma unroll
        for (int ni = 0; ni < 4; ni++)
            #pragma unroll
            for (int q = 0; q < 4; q++) c[mi][ni][q] = 0.f;

    const int ar0 = tid >> 3,  ac0 = (tid & 7) << 2;
    const int ar1 = (tid + 256) >> 3, ac1 = ((tid + 256) & 7) << 2;
    float4 ra[2], rb[4];

    {
        int gr = row0 + ar0;
        ra[0] = make_float4(0.f, 0.f, 0.f, 0.f);
        if (gr < NN && ac0 + 4 <= FF) ra[0] = *(const float4*)(A + gr * FF + ac0);
        gr = row0 + ar1;
        ra[1] = make_float4(0.f, 0.f, 0.f, 0.f);
        if (gr < NN && ac1 + 4 <= FF) ra[1] = *(const float4*)(A + gr * FF + ac1);
        #pragma unroll
        for (int i = 0; i < 4; i++) {
            int lin = tid + i * 256;
            int br = lin >> 5, bc = (lin & 31) << 2;
            rb[i] = *(const float4*)(g_Wg + br * H1D + bc);
        }
        split_store4(ra[0], bAh + ar0 * AST + ac0, bAl + ar0 * AST + ac0);
        split_store4(ra[1], bAh + ar1 * AST + ac1, bAl + ar1 * AST + ac1);
        #pragma unroll
        for (int i = 0; i < 4; i++) {
            int lin = tid + i * 256;
            int br = lin >> 5, bc = (lin & 31) << 2;
            split_store4(rb[i], bBh + br * BST + bc, bBl + br * BST + bc);
        }
    }
    __syncthreads();

    {
        int gr = row0 + ar0, gc = 32 + ac0;
        ra[0] = make_float4(0.f, 0.f, 0.f, 0.f);
        if (gr < NN && gc + 4 <= FF) ra[0] = *(const float4*)(A + gr * FF + gc);
        gr = row0 + ar1; gc = 32 + ac1;
        ra[1] = make_float4(0.f, 0.f, 0.f, 0.f);
        if (gr < NN && gc + 4 <= FF) ra[1] = *(const float4*)(A + gr * FF + gc);
        #pragma unroll
        for (int i = 0; i < 4; i++) {
            int lin = tid + i * 256;
            int br = lin >> 5, bc = (lin & 31) << 2;
            rb[i] = *(const float4*)(g_Wg + (32 + br) * H1D + bc);
        }
    }

    int p = 0;
    for (int k0 = 0; k0 < KPAD; k0 += 32) {
        const __nv_bfloat16* sAh = bAh + p * A_ELEM;
        const __nv_bfloat16* sAl = bAl + p * A_ELEM;
        const __nv_bfloat16* sBh = bBh + p * B_ELEM;
        const __nv_bfloat16* sBl = bBl + p * B_ELEM;

        #pragma unroll
        for (int kk = 0; kk < 32; kk += 16) {
            uint ah[2][4], al[2][4], bh[4][2], bl[4][2];
            #pragma unroll
            for (int mi = 0; mi < 2; mi++) {
                const __nv_bfloat16* pa = sAh + (wm + mi * 16 + (lane & 15)) * AST + kk + ((lane >> 4) << 3);
                ldsm_x4(ah[mi][0], ah[mi][1], ah[mi][2], ah[mi][3], pa);
                const __nv_bfloat16* pb = sAl + (wm + mi * 16 + (lane & 15)) * AST + kk + ((lane >> 4) << 3);
                ldsm_x4(al[mi][0], al[mi][1], al[mi][2], al[mi][3], pb);
            }
            #pragma unroll
            for (int ni = 0; ni < 4; ni += 2) {
                const __nv_bfloat16* pbh = sBh + (kk + (lane & 15)) * BST + wn + ni * 8 + ((lane >> 4) << 3);
                ldsm_x4t(bh[ni][0], bh[ni][1], bh[ni + 1][0], bh[ni + 1][1], pbh);
                const __nv_bfloat16* pbl = sBl + (kk + (lane & 15)) * BST + wn + ni * 8 + ((lane >> 4) << 3);
                ldsm_x4t(bl[ni][0], bl[ni][1], bl[ni + 1][0], bl[ni + 1][1], pbl);
            }
            #pragma unroll
            for (int mi = 0; mi < 2; mi++)
                #pragma unroll
                for (int ni = 0; ni < 4; ni++) {
                    mma16816(c[mi][ni], ah[mi], bh[ni]);
                    mma16816(c[mi][ni], ah[mi], bl[ni]);
                    mma16816(c[mi][ni], al[mi], bh[ni]);
                }
        }

        int kn = k0 + 32;
        if (kn < KPAD) {
            __nv_bfloat16* dAh = bAh + (p ^ 1) * A_ELEM;
            __nv_bfloat16* dAl = bAl + (p ^ 1) * A_ELEM;
            __nv_bfloat16* dBh = bBh + (p ^ 1) * B_ELEM;
            __nv_bfloat16* dBl = bBl + (p ^ 1) * B_ELEM;
            split_store4(ra[0], dAh + ar0 * AST + ac0, dAl + ar0 * AST + ac0);
            split_store4(ra[1], dAh + ar1 * AST + ac1, dAl + ar1 * AST + ac1);
            #pragma unroll
            for (int i = 0; i < 4; i++) {
                int lin = tid + i * 256;
                int br = lin >> 5, bc = (lin & 31) << 2;
                split_store4(rb[i], dBh + br * BST + bc, dBl + br * BST + bc);
            }
            int km = kn + 32;
            if (km < KPAD) {
                int gr = row0 + ar0, gc = km + ac0;
                ra[0] = make_float4(0.f, 0.f, 0.f, 0.f);
                if (gr < NN && gc + 4 <= FF) ra[0] = *(const float4*)(A + gr * FF + gc);
                gr = row0 + ar1; gc = km + ac1;
                ra[1] = make_float4(0.f, 0.f, 0.f, 0.f);
                if (gr < NN && gc + 4 <= FF) ra[1] = *(const float4*)(A + gr * FF + gc);
                #pragma unroll
                for (int i = 0; i < 4; i++) {
                    int lin = tid + i * 256;
                    int br = lin >> 5, bc = (lin & 31) << 2;
                    rb[i] = *(const float4*)(g_Wg + (km + br) * H1D + bc);
                }
            }
            __syncthreads();
        }
        p ^= 1;
    }

    #pragma unroll
    for (int mi = 0; mi < 2; mi++) {
        int r_lo = row0 + wm + mi * 16 + (lane >> 2);
        #pragma unroll
        for (int ni = 0; ni < 4; ni++) {
            int col = wn + ni * 8 + ((lane & 3) << 1);
            if (r_lo < NN)
                *(uint*)(g_xW1h + r_lo * H1D + col) = f2h(c[mi][ni][0], c[mi][ni][1]);
            if (r_lo + 8 < NN)
                *(uint*)(g_xW1h + (r_lo + 8) * H1D + col) = f2h(c[mi][ni][2], c[mi][ni][3]);
        }
    }
}

// ---------------- agg1: h1h = relu(Agg(xW1h) + b1), fp16 io -----------------
__global__ void k_agg1(const float* __restrict__ b1) {
    int n    = (blockIdx.x * blockDim.x + threadIdx.x) >> 5;
    int lane = threadIdx.x & 31;
    if (n >= NN) return;
    int r0 = g_rowptr[n], r1 = g_rowptr[n + 1];
    float4 s4 = make_float4(0.f, 0.f, 0.f, 0.f);
    int j = r0;
    for (; j + 1 < r1; j += 2) {
        int sa = g_csr[j], sb = g_csr[j + 1];
        float wa = g_dinv[sa], wb = g_dinv[sb];
        uint2 ua = *(const uint2*)(g_xW1h + sa * H1D + lane * 4);
        uint2 ub = *(const uint2*)(g_xW1h + sb * H1D + lane * 4);
        float2 a01 = h2f(ua.x), a23 = h2f(ua.y);
        float2 b01 = h2f(ub.x), b23 = h2f(ub.y);
        s4.x += wa * a01.x + wb * b01.x;
        s4.y += wa * a01.y + wb * b01.y;
        s4.z += wa * a23.x + wb * b23.x;
        s4.w += wa * a23.y + wb * b23.y;
    }
    if (j < r1) {
        int sa = g_csr[j];
        float wa = g_dinv[sa];
        uint2 ua = *(const uint2*)(g_xW1h + sa * H1D + lane * 4);
        float2 a01 = h2f(ua.x), a23 = h2f(ua.y);
        s4.x += wa * a01.x; s4.y += wa * a01.y; s4.z += wa * a23.x; s4.w += wa * a23.y;
    }
    float dn = g_dinv[n], dn2 = dn * dn;
    uint2 us = *(const uint2*)(g_xW1h + n * H1D + lane * 4);
    float2 s01 = h2f(us.x), s23 = h2f(us.y);
    float4 bv = *(const float4*)(b1 + lane * 4);
    float o0 = fmaxf(dn * s4.x + dn2 * s01.x + bv.x, 0.f);
    float o1 = fmaxf(dn * s4.y + dn2 * s01.y + bv.y, 0.f);
    float o2 = fmaxf(dn * s4.z + dn2 * s23.x + bv.z, 0.f);
    float o3 = fmaxf(dn * s4.w + dn2 * s23.y + bv.w, 0.f);
    *(uint2*)(g_h1h + n * H1D + lane * 4) = make_uint2(f2h(o0, o1), f2h(o2, o3));
}

// ---------------- GEMM2 (tensor, fp16-native A, fp16 hi/lo B) ---------------
// BM=64, BN=64, BK=32, 8 warps 2m x 4n (warp tile 32x16)
__global__ void __launch_bounds__(256, 2) k_gemm2(const float* __restrict__ W2) {
    __shared__ __align__(16) __half sA [64 * AST2];
    __shared__ __align__(16) __half sBh[32 * BST2];
    __shared__ __align__(16) __half sBl[32 * BST2];

    const int tid  = threadIdx.x;
    const int lane = tid & 31;
    const int wid  = tid >> 5;
    const int row0 = blockIdx.x * 64;
    const int wm = (wid & 1) * 32;       // 2 m-warps x (2 x 16) rows
    const int wn = (wid >> 1) * 16;      // 4 n-warps x 16 cols

    float c[2][2][4];
    #pragma unroll
    for (int mi = 0; mi < 2; mi++)
        #pragma unroll
        for (int ni = 0; ni < 2; ni++)
            #pragma unroll
            for (int q = 0; q < 4; q++) c[mi][ni][q] = 0.f;

    // A tile: 64x32 fp16, one uint4 (8 halfs) per thread
    const int ar = tid >> 2, ac8 = (tid & 3) << 3;

    for (int k0 = 0; k0 < H1D; k0 += 32) {
        // A: raw fp16 copy from g_h1h
        {
            uint4 v = make_uint4(0u, 0u, 0u, 0u);
            int gr = row0 + ar;
            if (gr < NN) v = *(const uint4*)(g_h1h + gr * H1D + k0 + ac8);
            *(uint4*)(sA + ar * AST2 + ac8) = v;
        }
        // B: W2 fp32 32x64 -> fp16 hi/lo (2 float4/thread)
        #pragma unroll
        for (int i = 0; i < 2; i++) {
            int lin = tid + i * 256;
            int br = lin >> 4, bc = (lin & 15) << 2;
            float4 w = *(const float4*)(W2 + (k0 + br) * H2D + bc);
            fp16split4(w, sBh + br * BST2 + bc, sBl + br * BST2 + bc);
        }
        __syncthreads();

        #pragma unroll
        for (int kk = 0; kk < 32; kk += 16) {
            uint a[2][4], bh[2][2], bl[2][2];
            #pragma unroll
            for (int mi = 0; mi < 2; mi++) {
                const __half* pa = sA + (wm + mi * 16 + (lane & 15)) * AST2 + kk + ((lane >> 4) << 3);
                ldsm_x4(a[mi][0], a[mi][1], a[mi][2], a[mi][3], pa);
            }
            {
                const __half* pbh = sBh + (kk + (lane & 15)) * BST2 + wn + ((lane >> 4) << 3);
                ldsm_x4t(bh[0][0], bh[0][1], bh[1][0], bh[1][1], pbh);
                const __half* pbl = sBl + (kk + (lane & 15)) * BST2 + wn + ((lane >> 4) << 3);
                ldsm_x4t(bl[0][0], bl[0][1], bl[1][0], bl[1][1], pbl);
            }
            #pragma unroll
            for (int mi = 0; mi < 2; mi++)
                #pragma unroll
                for (int ni = 0; ni < 2; ni++) {
                    mma16816h(c[mi][ni], a[mi], bh[ni]);
                    mma16816h(c[mi][ni], a[mi], bl[ni]);
                }
        }
        __syncthreads();
    }

    #pragma unroll
    for (int mi = 0; mi < 2; mi++) {
        int r_lo = row0 + wm + mi * 16 + (lane >> 2);
        #pragma unroll
        for (int ni = 0; ni < 2; ni++) {
            int col = wn + ni * 8 + ((lane & 3) << 1);
            if (r_lo < NN)
                *(uint*)(g_hl2h + r_lo * H2D + col) = f2h(c[mi][ni][0], c[mi][ni][1]);
            if (r_lo + 8 < NN)
                *(uint*)(g_hl2h + (r_lo + 8) * H2D + col) = f2h(c[mi][ni][2], c[mi][ni][3]);
        }
    }
}

// ---------------- agg2 + fused small3: feat (fp32 out) + feath + hl3 --------
__global__ void k_agg2(const float* __restrict__ b2, float* __restrict__ feat,
                       const float* __restrict__ Wr, const float* __restrict__ Wk) {
    __shared__ float sW[64 * 6];
    for (int t = threadIdx.x; t < 384; t += blockDim.x) {
        int k = t / 6, c = t % 6;
        sW[t] = (c < 3) ? Wr[k * 3 + c] : Wk[k * 3 + (c - 3)];
    }
    __syncthreads();

    int n    = (blockIdx.x * blockDim.x + threadIdx.x) >> 5;
    int lane = threadIdx.x & 31;
    if (n >= NN) return;
    int r0 = g_rowptr[n], r1 = g_rowptr[n + 1];
    float2 s2 = make_float2(0.f, 0.f);
    int j = r0;
    for (; j + 1 < r1; j += 2) {
        int sa = g_csr[j], sb = g_csr[j + 1];
        float wa = g_dinv[sa], wb = g_dinv[sb];
        float2 va = h2f(*(const uint*)(g_hl2h + sa * H2D + lane * 2));
        float2 vb = h2f(*(const uint*)(g_hl2h + sb * H2D + lane * 2));
        s2.x += wa * va.x + wb * vb.x;
        s2.y += wa * va.y + wb * vb.y;
    }
    if (j < r1) {
        int sa = g_csr[j];
        float wa = g_dinv[sa];
        float2 va = h2f(*(const uint*)(g_hl2h + sa * H2D + lane * 2));
        s2.x += wa * va.x; s2.y += wa * va.y;
    }
    float dn = g_dinv[n], dn2 = dn * dn;
    float2 self = h2f(*(const uint*)(g_hl2h + n * H2D + lane * 2));
    float2 bv   = *(const float2*)(b2 + lane * 2);
    float2 o;
    o.x = dn * s2.x + dn2 * self.x + bv.x;
    o.y = dn * s2.y + dn2 * self.y + bv.y;
    *(float2*)(feat + n * H2D + lane * 2) = o;
    *(uint*)(g_feath + n * H2D + lane * 2) = f2h(o.x, o.y);

    float p[6];
    #pragma unroll
    for (int c = 0; c < 6; c++)
        p[c] = o.x * sW[(2 * lane) * 6 + c] + o.y * sW[(2 * lane + 1) * 6 + c];
    #pragma unroll
    for (int off = 16; off > 0; off >>= 1) {
        #pragma unroll
        for (int c = 0; c < 6; c++)
            p[c] += __shfl_xor_sync(0xffffffffu, p[c], off);
    }
    if (lane == 0) {
        *(float4*)(g_hl3 + n * 8)     = make_float4(p[0], p[1], p[2], p[3]);
        *(float4*)(g_hl3 + n * 8 + 4) = make_float4(p[4], p[5], 0.f, 0.f);
    }
}

// ---------------- agg3 + log_softmax + outputs ------------------------------
__global__ void k_agg3(const float* __restrict__ ba, const float* __restrict__ bk,
                       float* __restrict__ attr_o, float* __restrict__ att_o) {
    int n = blockIdx.x * blockDim.x + threadIdx.x;
    if (n >= NN) return;
    int r0 = g_rowptr[n], r1 = g_rowptr[n + 1];
    float4 s0 = make_float4(0.f, 0.f, 0.f, 0.f);
    float2 s1 = make_float2(0.f, 0.f);
    for (int j = r0; j < r1; j++) {
        int s = g_csr[j];
        float w = g_dinv[s];
        float4 v0 = *(const float4*)(g_hl3 + s * 8);
        float2 v1 = *(const float2*)(g_hl3 + s * 8 + 4);
        s0.x += w * v0.x; s0.y += w * v0.y; s0.z += w * v0.z; s0.w += w * v0.w;
        s1.x += w * v1.x; s1.y += w * v1.y;
    }
    float dn = g_dinv[n], dn2 = dn * dn;
    float4 e0 = *(const float4*)(g_hl3 + n * 8);
    float2 e1 = *(const float2*)(g_hl3 + n * 8 + 4);
    float v0 = dn * s0.x + dn2 * e0.x + ba[0];
    float v1 = dn * s0.y + dn2 * e0.y + ba[1];
    float v2 = dn * s0.z + dn2 * e0.z + ba[2];
    float v3 = dn * s0.w + dn2 * e0.w + bk[0];
    float v4 = dn * s1.x + dn2 * e1.x + bk[1];
    float v5 = dn * s1.y + dn2 * e1.y + bk[2];
    float m  = fmaxf(v0, fmaxf(v1, v2));
    float ls = m + logf(expf(v0 - m) + expf(v1 - m) + expf(v2 - m));
    attr_o[n * 3 + 0] = v0 - ls;
    attr_o[n * 3 + 1] = v1 - ls;
    attr_o[n * 3 + 2] = v2 - ls;
    att_o[n * 3 + 0] = v3;
    att_o[n * 3 + 1] = v4;
    att_o[n * 3 + 2] = v5;
}

// ---------------- edge dot products (fp16 gather, 8 lanes x 16B) ------------
__global__ void k_dot(const int* __restrict__ pe, const int* __restrict__ ne,
                      float* __restrict__ res) {
    int t = blockIdx.x * blockDim.x + threadIdx.x;
    int e = t >> 3, l = t & 7;
    if (e >= 2 * PEE) return;
    int i, j;
    if (e < PEE) { j = pe[e];        i = pe[PEE + e]; }
    else         { j = ne[e - PEE];  i = ne[PEE + (e - PEE)]; }
    uint4 ua = *(const uint4*)(g_feath + i * H2D + l * 8);
    uint4 ub = *(const uint4*)(g_feath + j * H2D + l * 8);
    float2 a0 = h2f(ua.x), a1 = h2f(ua.y), a2 = h2f(ua.z), a3 = h2f(ua.w);
    float2 b0 = h2f(ub.x), b1 = h2f(ub.y), b2 = h2f(ub.z), b3 = h2f(ub.w);
    float p = a0.x * b0.x + a0.y * b0.y + a1.x * b1.x + a1.y * b1.y
            + a2.x * b2.x + a2.y * b2.y + a3.x * b3.x + a3.y * b3.y;
    p += __shfl_xor_sync(0xffffffffu, p, 4);
    p += __shfl_xor_sync(0xffffffffu, p, 2);
    p += __shfl_xor_sync(0xffffffffu, p, 1);
    if (l == 0) res[e] = p;
}

// ---------------- streams / events ------------------------------------------
static cudaStream_t g_s2;
static cudaEvent_t  g_evFork, g_evJoin, g_evFork2, g_evJoin2;
namespace {
struct StreamInit {
    StreamInit() {
        cudaStreamCreateWithFlags(&g_s2, cudaStreamNonBlocking);
        cudaEventCreateWithFlags(&g_evFork,  cudaEventDisableTiming);
        cudaEventCreateWithFlags(&g_evJoin,  cudaEventDisableTiming);
        cudaEventCreateWithFlags(&g_evFork2, cudaEventDisableTiming);
        cudaEventCreateWithFlags(&g_evJoin2, cudaEventDisableTiming);
        cudaFuncSetAttribute(k_gemm1, cudaFuncAttributeMaxDynamicSharedMemorySize,
                             G1_SMEM_BYTES);
    }
} s_streamInit;
}

// ---------------- launch -----------------------------------------------------
extern "C" void kernel_launch(void* const* d_in, const int* in_sizes, int n_in,
                              void* d_out, int out_size) {
    const float* x      = (const float*)d_in[0];
    const float* glove  = (const float*)d_in[1];
    const float* W1     = (const float*)d_in[2];
    const float* b1     = (const float*)d_in[3];
    const float* W2     = (const float*)d_in[4];
    const float* b2     = (const float*)d_in[5];
    const float* W_attr = (const float*)d_in[6];
    const float* b_attr = (const float*)d_in[7];
    const float* W_attk = (const float*)d_in[8];
    const float* b_attk = (const float*)d_in[9];
    const int*   ei     = (const int*)d_in[10];
    const int*   pe     = (const int*)d_in[11];
    const int*   ne     = (const int*)d_in[12];

    float* out    = (float*)d_out;
    float* res    = out;
    float* attr_o = out + 2 * PEE;
    float* att_o  = attr_o + NN * 3;
    float* feat   = att_o + NN * 3;

    const int* src = ei;
    const int* dst = ei + EE;

    k_init<<<(KPAD * H1D + 255) / 256, 256>>>();                       // 1 (main)
    cudaEventRecord(g_evFork, 0);
    cudaStreamWaitEvent(g_s2, g_evFork, 0);

    {
        dim3 g((FF * H1D + 255) / 256, KSEG);
        k_wg <<<g, 256>>>(glove, W1);                                  // 2 (main)
    }
    k_deg    <<<(EE + 255) / 256, 256, 0, g_s2>>>(dst);                // 3 (side)
    k_gemm1  <<<(NN + 63) / 64, 256, G1_SMEM_BYTES>>>(x);              // 4 (main)

    k_scan1  <<<SCAN_B, 256, 0, g_s2>>>();
    k_scan2  <<<1, 256, 0, g_s2>>>();
    k_scan3  <<<SCAN_B, 256, 0, g_s2>>>();
    k_scatter<<<(EE + 255) / 256, 256, 0, g_s2>>>(src, dst);
    cudaEventRecord(g_evJoin, g_s2);

    cudaStreamWaitEvent(0, g_evJoin, 0);

    k_agg1 <<<(NN * 32 + 255) / 256, 256>>>(b1);
    k_gemm2<<<(NN + 63) / 64, 256>>>(W2);
    k_agg2 <<<(NN * 32 + 255) / 256, 256>>>(b2, feat, W_attr, W_attk);

    cudaEventRecord(g_evFork2, 0);
    cudaStreamWaitEvent(g_s2, g_evFork2, 0);
    k_dot<<<(2 * PEE * 8 + 255) / 256, 256, 0, g_s2>>>(pe, ne, res);
    cudaEventRecord(g_evJoin2, g_s2);

    k_agg3<<<(NN + 255) / 256, 256>>>(b_attr, b_attk, attr_o, att_o);

    cudaStreamWaitEvent(0, g_evJoin2, 0);
}